// round 2
// baseline (speedup 1.0000x reference)
#include <cuda_runtime.h>
#include <cuda_bf16.h>
#include <math.h>

// Problem dims
#define D        1024
#define S        32768
#define VOCAB    50257
#define CDIM     2048

// K2 config: 256 blocks * 8 warps = 2048 warps, 16 rows each
#define ATT_BLOCKS 256
#define ATT_WARPS  8
#define ROWS_PER_WARP (S / (ATT_BLOCKS * ATT_WARPS))   // 16

// Scratch (device globals; no allocation allowed)
// partial layout per block: [0]=m, [1]=z, [4..1027]=acc (16B aligned: stride 1028 floats)
__device__ float g_part[ATT_BLOCKS * 1028];
__device__ float g_concat[CDIM];          // [0..1023]=x (relu hidden), [1024..2047]=attn
__device__ float g_logits[VOCAB];
__device__ float g_stats[2];              // M, 1/Z for final softmax

__device__ __forceinline__ float warp_reduce_sum(float v) {
#pragma unroll
    for (int o = 16; o > 0; o >>= 1) v += __shfl_xor_sync(0xffffffffu, v, o);
    return v;
}

// ---------------------------------------------------------------------------
// K1: x = relu(W_h @ input + b_h); one warp per output row. Writes g_concat[0..D)
// ---------------------------------------------------------------------------
__global__ void k1_hidden(const float* __restrict__ inp,
                          const float* __restrict__ Wh,
                          const float* __restrict__ bh) {
    int warp = threadIdx.x >> 5, lane = threadIdx.x & 31;
    int row  = blockIdx.x * 16 + warp;     // 64 blocks * 16 warps = 1024 rows
    const float4* w4  = (const float4*)(Wh + (size_t)row * D);
    const float4* in4 = (const float4*)inp;
    float acc = 0.f;
#pragma unroll
    for (int k = 0; k < 8; k++) {
        float4 a = w4[k * 32 + lane];
        float4 b = in4[k * 32 + lane];
        acc += a.x * b.x + a.y * b.y + a.z * b.z + a.w * b.w;
    }
    acc = warp_reduce_sum(acc);
    if (lane == 0) g_concat[row] = fmaxf(acc + bh[row], 0.f);
}

// ---------------------------------------------------------------------------
// K2: fused flash-style attention over encoder_outputs (single 134 MB pass).
// Each warp streams 16 rows; per-lane 32-float distributed accumulator.
// Block-combines 8 warp partials -> g_part[block].
// ---------------------------------------------------------------------------
__global__ void k2_attn(const float* __restrict__ enc) {
    __shared__ float4 sq[D / 4];              // q (= x) as float4        : 4 KB
    __shared__ float  swacc[ATT_WARPS * D];   // per-warp scaled accums   : 32 KB
    __shared__ float  sm_[ATT_WARPS];
    __shared__ float  sz_[ATT_WARPS];

    int tid = threadIdx.x, warp = tid >> 5, lane = tid & 31;

    for (int i = tid; i < D / 4; i += blockDim.x)
        sq[i] = ((const float4*)g_concat)[i];
    __syncthreads();

    int gw   = blockIdx.x * ATT_WARPS + warp;
    int row0 = gw * ROWS_PER_WARP;

    float  m = -INFINITY, z = 0.f;
    float4 acc[8];
#pragma unroll
    for (int k = 0; k < 8; k++) acc[k] = make_float4(0.f, 0.f, 0.f, 0.f);

    for (int r = 0; r < ROWS_PER_WARP; r++) {
        const float4* e4 = (const float4*)(enc + (size_t)(row0 + r) * D);
        float4 rv[8];
        float  p = 0.f;
#pragma unroll
        for (int k = 0; k < 8; k++) {
            rv[k] = e4[k * 32 + lane];
            float4 qv = sq[k * 32 + lane];
            p += rv[k].x * qv.x + rv[k].y * qv.y + rv[k].z * qv.z + rv[k].w * qv.w;
        }
        p = warp_reduce_sum(p);               // score for this row (all lanes)

        float nm = fmaxf(m, p);
        float sc = __expf(m - nm);
        float w  = __expf(p - nm);
#pragma unroll
        for (int k = 0; k < 8; k++) {
            acc[k].x = acc[k].x * sc + w * rv[k].x;
            acc[k].y = acc[k].y * sc + w * rv[k].y;
            acc[k].z = acc[k].z * sc + w * rv[k].z;
            acc[k].w = acc[k].w * sc + w * rv[k].w;
        }
        z = z * sc + w;
        m = nm;
    }

    if (lane == 0) sm_[warp] = m;
    __syncthreads();

    float mb = sm_[0];
#pragma unroll
    for (int wv = 1; wv < ATT_WARPS; wv++) mb = fmaxf(mb, sm_[wv]);

    float f = __expf(m - mb);
    if (lane == 0) sz_[warp] = z * f;
#pragma unroll
    for (int k = 0; k < 8; k++) {
        float4 s = make_float4(acc[k].x * f, acc[k].y * f, acc[k].z * f, acc[k].w * f);
        ((float4*)swacc)[warp * (D / 4) + k * 32 + lane] = s;
    }
    __syncthreads();

    // Reduce 8 warp partials; thread tid handles one float4 column group
    float* outp = &g_part[blockIdx.x * 1028];
    float4 s = make_float4(0.f, 0.f, 0.f, 0.f);
#pragma unroll
    for (int wv = 0; wv < ATT_WARPS; wv++) {
        float4 v = ((float4*)swacc)[wv * (D / 4) + tid];
        s.x += v.x; s.y += v.y; s.z += v.z; s.w += v.w;
    }
    ((float4*)(outp + 4))[tid] = s;           // offset 4 floats = 16B aligned
    if (tid == 0) {
        float zz = 0.f;
#pragma unroll
        for (int wv = 0; wv < ATT_WARPS; wv++) zz += sz_[wv];
        outp[0] = mb;
        outp[1] = zz;
    }
}

// ---------------------------------------------------------------------------
// K3: combine ATT_BLOCKS partials -> attn vector; writes g_concat[D..2D)
// 8 blocks x 128 threads; every block redundantly computes M and Z (cheap).
// ---------------------------------------------------------------------------
__global__ void k3_combine() {
    __shared__ float sf[ATT_BLOCKS];
    __shared__ float red[128];
    int tid = threadIdx.x;

    float lm = -INFINITY;
    for (int b = tid; b < ATT_BLOCKS; b += 128) lm = fmaxf(lm, g_part[b * 1028]);
    red[tid] = lm; __syncthreads();
    for (int s = 64; s > 0; s >>= 1) {
        if (tid < s) red[tid] = fmaxf(red[tid], red[tid + s]);
        __syncthreads();
    }
    float M = red[0]; __syncthreads();

    float lz = 0.f;
    for (int b = tid; b < ATT_BLOCKS; b += 128) {
        float fb = __expf(g_part[b * 1028] - M);
        sf[b] = fb;
        lz += fb * g_part[b * 1028 + 1];
    }
    red[tid] = lz; __syncthreads();
    for (int s = 64; s > 0; s >>= 1) {
        if (tid < s) red[tid] += red[tid + s];
        __syncthreads();
    }
    float invZ = 1.0f / red[0];
    __syncthreads();

    int d = blockIdx.x * 128 + tid;
    float v = 0.f;
    for (int b = 0; b < ATT_BLOCKS; b++) v += sf[b] * g_part[b * 1028 + 4 + d];
    g_concat[D + d] = v * invZ;
}

// ---------------------------------------------------------------------------
// K4: logits = W_out @ concat + b_out; one warp per vocab row (412 MB pass)
// 512 threads = 16 warps per block -> 3142 blocks
// ---------------------------------------------------------------------------
__global__ void k4_logits(const float* __restrict__ Wo,
                          const float* __restrict__ bo) {
    __shared__ float4 sc[CDIM / 4];           // 8 KB
    int tid = threadIdx.x, warp = tid >> 5, lane = tid & 31;
    for (int i = tid; i < CDIM / 4; i += blockDim.x)
        sc[i] = ((const float4*)g_concat)[i];
    __syncthreads();

    int v = blockIdx.x * 16 + warp;
    if (v >= VOCAB) return;
    const float4* w4 = (const float4*)(Wo + (size_t)v * CDIM);
    float p = 0.f;
#pragma unroll
    for (int k = 0; k < 16; k++) {
        float4 a = w4[k * 32 + lane];
        float4 q = sc[k * 32 + lane];
        p += a.x * q.x + a.y * q.y + a.z * q.z + a.w * q.w;
    }
    p = warp_reduce_sum(p);
    if (lane == 0) g_logits[v] = p + bo[v];
}

// ---------------------------------------------------------------------------
// K5: softmax stats (max, 1/sumexp) over 50257 logits — single block
// ---------------------------------------------------------------------------
__global__ void k5_stats() {
    __shared__ float red[1024];
    int tid = threadIdx.x;
    float lm = -INFINITY;
    for (int i = tid; i < VOCAB; i += 1024) lm = fmaxf(lm, g_logits[i]);
    red[tid] = lm; __syncthreads();
    for (int s = 512; s > 0; s >>= 1) {
        if (tid < s) red[tid] = fmaxf(red[tid], red[tid + s]);
        __syncthreads();
    }
    float M = red[0]; __syncthreads();
    float lz = 0.f;
    for (int i = tid; i < VOCAB; i += 1024) lz += __expf(g_logits[i] - M);
    red[tid] = lz; __syncthreads();
    for (int s = 512; s > 0; s >>= 1) {
        if (tid < s) red[tid] += red[tid + s];
        __syncthreads();
    }
    if (tid == 0) { g_stats[0] = M; g_stats[1] = 1.0f / red[0]; }
}

// ---------------------------------------------------------------------------
// K6: write softmax probabilities
// ---------------------------------------------------------------------------
__global__ void k6_out(float* __restrict__ out) {
    int i = blockIdx.x * 256 + threadIdx.x;
    if (i < VOCAB) out[i] = __expf(g_logits[i] - g_stats[0]) * g_stats[1];
}

// ---------------------------------------------------------------------------
extern "C" void kernel_launch(void* const* d_in, const int* in_sizes, int n_in,
                              void* d_out, int out_size) {
    const float* inp = (const float*)d_in[0];   // [1,1,1024]
    const float* enc = (const float*)d_in[1];   // [32768,1024]
    const float* Wh  = (const float*)d_in[2];   // [1024,1024]
    const float* bh  = (const float*)d_in[3];   // [1024]
    const float* Wo  = (const float*)d_in[4];   // [50257,2048]
    const float* bo  = (const float*)d_in[5];   // [50257]
    float* out = (float*)d_out;                 // [1,50257]

    k1_hidden<<<D / 16, 512>>>(inp, Wh, bh);
    k2_attn<<<ATT_BLOCKS, 256>>>(enc);
    k3_combine<<<D / 128, 128>>>();
    k4_logits<<<(VOCAB + 15) / 16, 512>>>(Wo, bo);
    k5_stats<<<1, 1024>>>();
    k6_out<<<(VOCAB + 255) / 256, 256>>>(out);
}